// round 15
// baseline (speedup 1.0000x reference)
#include <cuda_runtime.h>
#include <cuda_fp16.h>

#define Bx 64
#define Pz 32
#define ATTR 7
#define Cc 224      // A*P*ATTR
#define Rr 4096
#define NLAB 32
#define GRID 1024
#define TPB 256

// accumulators: xy, wl, rot, obj, noobj (zero-init at load; reset by last block each call)
__device__ double g_acc[5];
__device__ unsigned int g_done;

// -max(log(1 - sigmoid(x)), -100) == softplus(x), numerically stable
__device__ __forceinline__ float softplus_fast(float x) {
    return fmaxf(x, 0.0f) + __logf(1.0f + __expf(-fabsf(x)));
}
__device__ __forceinline__ float tanh_approx(float x) {
    float y;
    asm("tanh.approx.f32 %0, %1;" : "=f"(y) : "f"(x));
    return y;
}
__device__ __forceinline__ float sigmoid_fast(float x) {
    return 1.0f / (1.0f + __expf(-x));
}

__global__ void __launch_bounds__(TPB) yolo_fused_kernel(
    const float* __restrict__ preds, const float* __restrict__ labels,
    float* __restrict__ out)
{
    __shared__ int s_key[32];
    __shared__ float red[TPB / 32];

    // ---------- Part 1: object-cell terms (blocks 0..63, warp 0) — fp32, unchanged ----------
    if (blockIdx.x < Bx && threadIdx.x < 32) {
        int b = blockIdx.x, t = threadIdx.x;
        const float* lab = labels + (b * NLAB + t) * ATTR;
        float l0 = lab[0], l1 = lab[1], l2 = lab[2], l3 = lab[3],
              l4 = lab[4], l5 = lab[5];

        float ang = l0 + 204.8f;          // + R*CELL_ANGLE/2
        float q   = ang / 0.1f;           // / CELL_ANGLE
        int i = (int)floorf(q);
        i = min(max(i, 0), Rr - 1);
        float dq = l1;                    // / CELL_DEPTH (=1.0)
        int j = (int)floorf(dq);
        j = min(max(j, 0), Pz - 1);

        int key = i * Pz + j;
        s_key[t] = key;
        __syncwarp();
        bool active = true;               // last-write-wins dedup
        for (int u = t + 1; u < 32; u++)
            if (s_key[u] == key) active = false;

        float sxy = 0.f, swl = 0.f, srot = 0.f, sobj = 0.f, scorr = 0.f;
        if (active) {
            const float* pp = preds + ((size_t)b * Cc + (size_t)j * ATTR) * Rr + i;
            float x0 = pp[0 * Rr], x1 = pp[1 * Rr], x2 = pp[2 * Rr],
                  x3 = pp[3 * Rr], x4 = pp[4 * Rr], x5 = pp[5 * Rr],
                  x6 = pp[6 * Rr];

            float tx = q - (float)i;
            float ty = dq - (float)j;
            float sx = sigmoid_fast(x0);
            float sy = sigmoid_fast(x1);
            sxy = (sx - tx) * (sx - tx) + (sy - ty) * (sy - ty);

            float tw = __logf(l2 * 0.625f + 1e-16f);        // /1.6
            float tl = __logf(l3 * 0.2564102564f + 1e-16f); // /3.9
            swl = (x2 - tw) * (x2 - tw) + (x3 - tl) * (x3 - tl);

            float r0 = tanh_approx(x4), r1 = tanh_approx(x5);
            srot = (r0 - l4) * (r0 - l4) + (r1 - l5) * (r1 - l5);

            // -log(sigmoid(x)) = softplus(-x); log(1-sigmoid(x)) = -softplus(x)
            sobj  = softplus_fast(-x6);
            scorr = -softplus_fast(x6);   // remove this cell from dense noobj sum
        }
        #pragma unroll
        for (int off = 16; off; off >>= 1) {
            sxy   += __shfl_xor_sync(0xffffffffu, sxy,   off);
            swl   += __shfl_xor_sync(0xffffffffu, swl,   off);
            srot  += __shfl_xor_sync(0xffffffffu, srot,  off);
            sobj  += __shfl_xor_sync(0xffffffffu, sobj,  off);
            scorr += __shfl_xor_sync(0xffffffffu, scorr, off);
        }
        if (t == 0) {
            atomicAdd(&g_acc[0], (double)sxy);
            atomicAdd(&g_acc[1], (double)swl);
            atomicAdd(&g_acc[2], (double)srot);
            atomicAdd(&g_acc[3], (double)sobj);
            atomicAdd(&g_acc[4], (double)scorr);
        }
    }

    // ---------- Part 2: dense noobj BCE — R4 loads, fp16x2 EX2 + log-of-product4 ----------
    // Sum softplus(x) = Sum max(x,0) + ln2 * Sum log2( prod4 (1 + 2^{-|x|·log2e}) )
    // MUFU: 2.0/elt -> 0.75/elt (two h2exp2 + one LG2 per 4 elements); FMA-pipe
    // cost unchanged (packs/HADD2/HMUL2 replace the per-element FADD/FMUL chain).
    {
        unsigned tid  = blockIdx.x * TPB + threadIdx.x;
        unsigned gw   = tid >> 5;            // global warp 0..8191
        unsigned lane = tid & 31;
        unsigned row  = gw >> 2;             // 0..2047  (= b*32 + ch)
        unsigned part = gw & 3;
        unsigned b    = row >> 5;
        unsigned ch   = row & 31;
        const float4* p4 = (const float4*)preds;
        const float4* bp = p4 + ((size_t)(b * Cc + ch * ATTR + 6)) * (Rr / 4)
                              + part * 256 + lane;

        float4 d0 = bp[0],   d1 = bp[32],  d2 = bp[64],  d3 = bp[96];
        float4 d4 = bp[128], d5 = bp[160], d6 = bp[192], d7 = bp[224];

        const half2 ONE2 = __float2half2_rn(1.0f);
        const float NL2E = -1.4426950408889634f;   // -log2(e)
        float m0 = 0.f, m1 = 0.f;       // sums of max(x,0)
        float gA = 0.f, gB = 0.f;       // sums of log2(prod4)

        #define ACC4(d, m, g)                                                 \
        {                                                                     \
            m += (fmaxf((d).x, 0.f) + fmaxf((d).y, 0.f))                      \
               + (fmaxf((d).z, 0.f) + fmaxf((d).w, 0.f));                     \
            half2 hz0 = __floats2half2_rn(NL2E * fabsf((d).x),                \
                                          NL2E * fabsf((d).y));               \
            half2 hz1 = __floats2half2_rn(NL2E * fabsf((d).z),                \
                                          NL2E * fabsf((d).w));               \
            half2 t0 = h2exp2(hz0);                                           \
            half2 t1 = h2exp2(hz1);                                           \
            half2 p  = __hmul2(__hadd2(ONE2, t0), __hadd2(ONE2, t1));         \
            half2 q2 = __hmul2(p, __lowhigh2highlow(p));                      \
            g += __log2f(__low2float(q2));                                    \
        }

        ACC4(d0, m0, gA) ACC4(d1, m1, gB) ACC4(d2, m0, gA) ACC4(d3, m1, gB)
        ACC4(d4, m0, gA) ACC4(d5, m1, gB) ACC4(d6, m0, gA) ACC4(d7, m1, gB)
        #undef ACC4

        float s = (m0 + m1) + 0.6931471805599453f * (gA + gB);

        #pragma unroll
        for (int off = 16; off; off >>= 1)
            s += __shfl_xor_sync(0xffffffffu, s, off);
        int wid = threadIdx.x >> 5, lid = threadIdx.x & 31;
        if (lid == 0) red[wid] = s;
        __syncthreads();
        if (wid == 0) {
            s = (lid < TPB / 32) ? red[lid] : 0.f;
            #pragma unroll
            for (int off = 4; off; off >>= 1)
                s += __shfl_xor_sync(0xffffffffu, s, off);
            if (lid == 0) atomicAdd(&g_acc[4], (double)s);
        }
    }

    // ---------- Part 3: last block finalizes + resets state ----------
    if (threadIdx.x == 0) {
        __threadfence();
        unsigned prev = atomicAdd(&g_done, 1u);
        if (prev == GRID - 1) {
            __threadfence();
            double a0 = *((volatile double*)&g_acc[0]);
            double a1 = *((volatile double*)&g_acc[1]);
            double a2 = *((volatile double*)&g_acc[2]);
            double a3 = *((volatile double*)&g_acc[3]);
            double a4 = *((volatile double*)&g_acc[4]);
            float lxy = (float)a0, lwl = (float)a1, lrot = (float)a2,
                  lobj = (float)a3, lnoobj = (float)a4;
            out[0] = 10.0f * lxy + 10.0f * lwl + 20.0f * lrot +
                     20.0f * lobj + 1.0f * lnoobj;
            out[1] = lxy;
            out[2] = lwl;
            out[3] = lrot;
            out[4] = lobj;
            out[5] = lnoobj;
            g_acc[0] = 0.0; g_acc[1] = 0.0; g_acc[2] = 0.0;
            g_acc[3] = 0.0; g_acc[4] = 0.0;
            g_done = 0u;
            __threadfence();
        }
    }
}

extern "C" void kernel_launch(void* const* d_in, const int* in_sizes, int n_in,
                              void* d_out, int out_size) {
    const float* preds  = (const float*)d_in[0];
    const float* labels = (const float*)d_in[1];
    float* out = (float*)d_out;

    yolo_fused_kernel<<<GRID, TPB>>>(preds, labels, out);
}